// round 1
// baseline (speedup 1.0000x reference)
#include <cuda_runtime.h>
#include <math.h>

#define NN 8192
#define DD 128
#define DEG 26
#define NC (DEG + 1)

// ---------------- scratch (device globals; no allocations) ----------------
__device__ float g_Xd[NN * DD];      // Z @ W_D^T
__device__ float g_Xc[NN * DD];      // Z @ W_C^T
__device__ float g_Hh[NN * DD];      // tanh(Z @ W1^T + b1)
__device__ float g_rea[NN * DD];     // H @ W2^T + b2
__device__ float g_s[NN];            // Z @ w_V
__device__ float g_red[2];           // s min / max
__device__ float g_B[32 * 32];       // separable poly combination matrix
__device__ float g_scal[8];          // omega, delta, center, inv2h
__device__ float g_part[64 * NC * DD];
__device__ float g_Hl[NC * DD];
__device__ float g_hl[NC];

// ---------------- 64x128 register-tiled SGEMM: Out = act(In @ W^T + b) ----
__device__ __forceinline__ void gemm_tile(const float* __restrict__ In,
                                          const float* __restrict__ W,
                                          const float* __restrict__ bias,
                                          float* __restrict__ Out,
                                          int row0, bool doTanh) {
    __shared__ float Zs[32][68];
    __shared__ float Ws[32][132];
    const int tid = threadIdx.x;           // 256 threads
    const int tx = tid & 31, ty = tid >> 5;
    const int c0 = tx * 4, r0 = ty * 8;
    float4 acc[8];
#pragma unroll
    for (int i = 0; i < 8; i++) acc[i] = make_float4(0.f, 0.f, 0.f, 0.f);

    for (int kc = 0; kc < 128; kc += 32) {
#pragma unroll
        for (int i = 0; i < 8; i++) {      // 64x32 input tile
            int idx = tid + i * 256;
            int r = idx >> 5, k = idx & 31;
            Zs[k][r] = In[(size_t)(row0 + r) * 128 + kc + k];
        }
#pragma unroll
        for (int i = 0; i < 16; i++) {     // 128x32 weight tile (transposed)
            int idx = tid + i * 256;
            int c = idx >> 5, k = idx & 31;
            Ws[k][c] = W[(size_t)c * 128 + kc + k];
        }
        __syncthreads();
#pragma unroll
        for (int k = 0; k < 32; k++) {
            float4 w  = *(const float4*)&Ws[k][c0];
            float4 z0 = *(const float4*)&Zs[k][r0];
            float4 z1 = *(const float4*)&Zs[k][r0 + 4];
            acc[0].x += z0.x * w.x; acc[0].y += z0.x * w.y; acc[0].z += z0.x * w.z; acc[0].w += z0.x * w.w;
            acc[1].x += z0.y * w.x; acc[1].y += z0.y * w.y; acc[1].z += z0.y * w.z; acc[1].w += z0.y * w.w;
            acc[2].x += z0.z * w.x; acc[2].y += z0.z * w.y; acc[2].z += z0.z * w.z; acc[2].w += z0.z * w.w;
            acc[3].x += z0.w * w.x; acc[3].y += z0.w * w.y; acc[3].z += z0.w * w.z; acc[3].w += z0.w * w.w;
            acc[4].x += z1.x * w.x; acc[4].y += z1.x * w.y; acc[4].z += z1.x * w.z; acc[4].w += z1.x * w.w;
            acc[5].x += z1.y * w.x; acc[5].y += z1.y * w.y; acc[5].z += z1.y * w.z; acc[5].w += z1.y * w.w;
            acc[6].x += z1.z * w.x; acc[6].y += z1.z * w.y; acc[6].z += z1.z * w.z; acc[6].w += z1.z * w.w;
            acc[7].x += z1.w * w.x; acc[7].y += z1.w * w.y; acc[7].z += z1.w * w.z; acc[7].w += z1.w * w.w;
        }
        __syncthreads();
    }
    float4 bv = make_float4(0.f, 0.f, 0.f, 0.f);
    if (bias) bv = *(const float4*)&bias[c0];
#pragma unroll
    for (int i = 0; i < 8; i++) {
        float4 v = acc[i];
        v.x += bv.x; v.y += bv.y; v.z += bv.z; v.w += bv.w;
        if (doTanh) { v.x = tanhf(v.x); v.y = tanhf(v.y); v.z = tanhf(v.z); v.w = tanhf(v.w); }
        *(float4*)&Out[(size_t)(row0 + r0 + i) * 128 + c0] = v;
    }
}

__global__ void k_gemm3(const float* __restrict__ Z, const float* __restrict__ WD,
                        const float* __restrict__ WC, const float* __restrict__ W1,
                        const float* __restrict__ b1) {
    int which = blockIdx.x >> 7;
    int row0 = (blockIdx.x & 127) * 64;
    if (which == 0)      gemm_tile(Z, WD, nullptr, g_Xd, row0, false);
    else if (which == 1) gemm_tile(Z, WC, nullptr, g_Xc, row0, false);
    else                 gemm_tile(Z, W1, b1,      g_Hh, row0, true);
}

__global__ void k_rea(const float* __restrict__ W2, const float* __restrict__ b2) {
    gemm_tile(g_Hh, W2, b2, g_rea, blockIdx.x * 64, false);
}

// ---------------- s = Z @ w_V (warp per row) ----------------
__global__ void k_s(const float* __restrict__ Z, const float* __restrict__ wv) {
    int warp = (blockIdx.x * blockDim.x + threadIdx.x) >> 5;
    int lane = threadIdx.x & 31;
    const float* z = Z + (size_t)warp * 128;
    float acc = z[lane] * wv[lane] + z[lane + 32] * wv[lane + 32] +
                z[lane + 64] * wv[lane + 64] + z[lane + 96] * wv[lane + 96];
#pragma unroll
    for (int o = 16; o > 0; o >>= 1) acc += __shfl_xor_sync(0xffffffffu, acc, o);
    if (lane == 0) g_s[warp] = acc;
}

// ---------------- min/max of s ----------------
__global__ void k_minmax() {
    __shared__ float slo[1024], shi[1024];
    int t = threadIdx.x;
    float lo = 1e30f, hi = -1e30f;
    for (int j = t; j < NN; j += 1024) { float v = g_s[j]; lo = fminf(lo, v); hi = fmaxf(hi, v); }
    slo[t] = lo; shi[t] = hi; __syncthreads();
    for (int st = 512; st > 0; st >>= 1) {
        if (t < st) { slo[t] = fminf(slo[t], slo[t + st]); shi[t] = fmaxf(shi[t], shi[t + st]); }
        __syncthreads();
    }
    if (t == 0) { g_red[0] = slo[0]; g_red[1] = shi[0]; }
}

// ---------------- polynomial fit of f(x)=exp(sigmoid(x)) on the exact range --
// v = (s_i - s_j) / (2*half) in [-1,1]; sigma = (s - center)/(2*half) in [-.5,.5]
// f(2*half*v) ~= sum_k b_k v^k  (degree-26 Chebyshev, built in fp64)
// B[l][p] = b_{l+p} * C(l+p, l) * (-1)^p  gives the separable form.
__global__ void k_setup(const float* __restrict__ om_l, const float* __restrict__ dl_l) {
    const int t = threadIdx.x; // 64 threads
    __shared__ double cs[NC];
    __shared__ double red[64];
    __shared__ double bm[32], mprev[32], mcur[32], mnext[32];
    double lo = (double)g_red[0], hi = (double)g_red[1];
    double center = 0.5 * (lo + hi);
    double half = 0.5 * (hi - lo) + 1e-12;
    const double PI = 3.14159265358979323846;
    double theta = PI * (t + 0.5) / 64.0;
    double vm = cos(theta);
    double fm = exp(1.0 / (1.0 + exp(-2.0 * half * vm)));

    double Tprev = 1.0, Tcur = vm;
    for (int k = 0; k < NC; k++) {
        double Tk;
        if (k == 0) Tk = 1.0;
        else if (k == 1) Tk = vm;
        else { Tk = 2.0 * vm * Tcur - Tprev; Tprev = Tcur; Tcur = Tk; }
        red[t] = fm * Tk;
        __syncthreads();
        for (int st = 32; st > 0; st >>= 1) { if (t < st) red[t] += red[t + st]; __syncthreads(); }
        if (t == 0) cs[k] = red[0] * (2.0 / 64.0) * (k == 0 ? 0.5 : 1.0);
        __syncthreads();
    }
    // Chebyshev -> monomial (in v), fp64
    if (t < 32) {
        mprev[t] = (t == 0) ? 1.0 : 0.0;
        mcur[t]  = (t == 1) ? 1.0 : 0.0;
        bm[t] = cs[0] * mprev[t] + cs[1] * mcur[t];
    }
    __syncthreads();
    for (int k = 2; k < NC; k++) {
        double nx = 0.0;
        if (t < 32) nx = ((t > 0) ? 2.0 * mcur[t - 1] : 0.0) - mprev[t];
        __syncthreads();
        if (t < 32) { mnext[t] = nx; bm[t] += cs[k] * nx; }
        __syncthreads();
        if (t < 32) { mprev[t] = mcur[t]; mcur[t] = mnext[t]; }
        __syncthreads();
    }
    for (int idx = t; idx < 32 * 32; idx += 64) {
        int l = idx >> 5, p = idx & 31;
        float val = 0.f;
        if (l <= DEG && p <= DEG - l) {
            double bb = 1.0;
            for (int q = 1; q <= l; q++) bb *= (double)(p + q) / (double)q;  // C(l+p, l)
            double v = bm[l + p] * bb;
            if (p & 1) v = -v;
            val = (float)v;
        }
        g_B[l * 32 + p] = val;
    }
    if (t == 0) {
        g_scal[0] = 1.f / (1.f + expf(-om_l[0]));  // omega
        g_scal[1] = 1.f / (1.f + expf(-dl_l[0]));  // delta
        g_scal[2] = (float)center;
        g_scal[3] = (float)(0.5 / half);           // 1/(2*half)
    }
}

// ---------------- moments G_p[d] = sum_j sigma_j^p * Xc[j,d] (partials) ------
__global__ void k_Gpart() {
    int d = threadIdx.x;   // 128
    int b = blockIdx.x;    // 64
    float center = g_scal[2], inv2h = g_scal[3];
    float acc[NC];
#pragma unroll
    for (int p = 0; p < NC; p++) acc[p] = 0.f;
    int j0 = b * 128;
    for (int jj = 0; jj < 128; jj++) {
        int j = j0 + jj;
        float sig = (g_s[j] - center) * inv2h;
        float x = g_Xc[(size_t)j * 128 + d];
        float pw = x;
#pragma unroll
        for (int p = 0; p < NC; p++) { acc[p] += pw; pw *= sig; }
    }
#pragma unroll
    for (int p = 0; p < NC; p++) g_part[((size_t)b * NC + p) * 128 + d] = acc[p];
}

// ---------------- reduce partials; H_l[d] = sum_p B[l][p] G_p[d]; h_l scalars -
__global__ void k_Hcomb() {
    int d = threadIdx.x;   // 128
    __shared__ float Gs[NC][DD];
    __shared__ float gpart[DD][NC];
    __shared__ float gtot[NC];
    for (int p = 0; p < NC; p++) {
        float sum = 0.f;
        for (int b = 0; b < 64; b++) sum += g_part[((size_t)b * NC + p) * 128 + d];
        Gs[p][d] = sum;
    }
    float center = g_scal[2], inv2h = g_scal[3];
    float gp[NC];
#pragma unroll
    for (int p = 0; p < NC; p++) gp[p] = 0.f;
    for (int jj = 0; jj < 64; jj++) {
        int j = d + jj * 128;
        float sig = (g_s[j] - center) * inv2h;
        float pw = 1.f;
#pragma unroll
        for (int p = 0; p < NC; p++) { gp[p] += pw; pw *= sig; }
    }
    for (int p = 0; p < NC; p++) gpart[d][p] = gp[p];
    __syncthreads();
    if (d < NC) {
        float s = 0.f;
        for (int tt = 0; tt < 128; tt++) s += gpart[tt][d];
        gtot[d] = s;
    }
    __syncthreads();
    for (int l = 0; l < NC; l++) {
        float sum = 0.f;
        for (int p = 0; p <= DEG - l; p++) sum += g_B[l * 32 + p] * Gs[p][d];
        g_Hl[l * 128 + d] = sum;
    }
    if (d < NC) {
        float sum = 0.f;
        for (int p = 0; p <= DEG - d; p++) sum += g_B[d * 32 + p] * gtot[p];
        g_hl[d] = sum;
    }
}

// ---------------- out = (1-omega)*con + delta*rea  (con via poly eval) ------
__global__ void k_final(float* __restrict__ out) {
    int d = threadIdx.x;   // 128
    __shared__ float Hs[NC * DD];
    __shared__ float hs[NC];
    for (int l = 0; l < NC; l++) Hs[l * 128 + d] = g_Hl[l * 128 + d];
    if (d < NC) hs[d] = g_hl[d];
    __syncthreads();
    float omega = g_scal[0], delta = g_scal[1], center = g_scal[2], inv2h = g_scal[3];
    int i0 = blockIdx.x * 64;
    for (int r = 0; r < 64; r++) {
        int i = i0 + r;
        float sig = (g_s[i] - center) * inv2h;
        float pw = 1.f, num = 0.f, den = 0.f;
#pragma unroll
        for (int l = 0; l < NC; l++) { num += pw * Hs[l * 128 + d]; den += pw * hs[l]; pw *= sig; }
        float con = num / den;
        out[(size_t)i * 128 + d] = (1.f - omega) * con + delta * g_rea[(size_t)i * 128 + d];
    }
}

// ---------------- out += omega * relu(A_norm @ Xd)  (sparse, warp per row) --
__global__ void k_spmm(const float* __restrict__ A, float* __restrict__ out) {
    int warp = (blockIdx.x * blockDim.x + threadIdx.x) >> 5;
    int lane = threadIdx.x & 31;
    const float4* Ar = (const float4*)(A + (size_t)warp * NN);
    const float4* X4 = (const float4*)g_Xd;
    float4 acc = make_float4(0.f, 0.f, 0.f, 0.f);
    for (int t = 0; t < 64; t++) {
        float4 a = Ar[t * 32 + lane];
        bool nz = (a.x != 0.f) || (a.y != 0.f) || (a.z != 0.f) || (a.w != 0.f);
        if (!__ballot_sync(0xffffffffu, nz)) continue;
#pragma unroll
        for (int c = 0; c < 4; c++) {
            float comp = (c == 0) ? a.x : (c == 1) ? a.y : (c == 2) ? a.z : a.w;
            unsigned m = __ballot_sync(0xffffffffu, comp != 0.f);
            while (m) {
                int b = __ffs(m) - 1; m &= m - 1;
                float av = __shfl_sync(0xffffffffu, comp, b);
                float4 x = X4[(size_t)((t * 32 + b) * 4 + c) * 32 + lane];
                acc.x += av * x.x; acc.y += av * x.y; acc.z += av * x.z; acc.w += av * x.w;
            }
        }
    }
    float omega = g_scal[0];
    float4* o = (float4*)out + (size_t)warp * 32 + lane;
    float4 v = *o;
    v.x += omega * fmaxf(acc.x, 0.f);
    v.y += omega * fmaxf(acc.y, 0.f);
    v.z += omega * fmaxf(acc.z, 0.f);
    v.w += omega * fmaxf(acc.w, 0.f);
    *o = v;
}

// ---------------- launch ----------------
extern "C" void kernel_launch(void* const* d_in, const int* in_sizes, int n_in,
                              void* d_out, int out_size) {
    const float* Z   = (const float*)d_in[0];
    const float* A   = (const float*)d_in[1];
    const float* W_D = (const float*)d_in[2];
    const float* W_C = (const float*)d_in[3];
    const float* w_V = (const float*)d_in[4];
    const float* W1  = (const float*)d_in[5];
    const float* b1  = (const float*)d_in[6];
    const float* W2  = (const float*)d_in[7];
    const float* b2  = (const float*)d_in[8];
    const float* omL = (const float*)d_in[9];
    const float* dlL = (const float*)d_in[10];
    float* out = (float*)d_out;

    k_gemm3<<<384, 256>>>(Z, W_D, W_C, W1, b1);
    k_s<<<1024, 256>>>(Z, w_V);
    k_rea<<<128, 256>>>(W2, b2);
    k_minmax<<<1, 1024>>>();
    k_setup<<<1, 64>>>(omL, dlL);
    k_Gpart<<<64, 128>>>();
    k_Hcomb<<<1, 128>>>();
    k_final<<<128, 128>>>(out);
    k_spmm<<<1024, 256>>>(A, out);
}